// round 16
// baseline (speedup 1.0000x reference)
#include <cuda_runtime.h>
#include <cuda_fp16.h>

// RROIAlign via fp16-NHWC re-layout + L2 eviction hints + PDL + CONCURRENT
// roi pairs: 512-thread gather block = 2 spatially-adjacent rois running in
// parallel (warps 0-7 / 8-15), co-located on one SM so overlapping corner
// lines dedup through L1 instead of hitting LTS twice. Spatial ordering via
// binning fused into transpose block (0,0,0) (hidden, free).

#define FB 2
#define FC 256
#define FH 200
#define FW 200
#define PER_ROI 12544      // 256*49
#define NROI 512

__device__ __half g_h[(size_t)FB * FH * FW * FC];   // 41 MB scratch
__device__ int    g_order[NROI];

static __device__ __forceinline__ __half2 u2h(unsigned u) {
    __half2 h; *reinterpret_cast<unsigned*>(&h) = u; return h;
}

static __device__ __forceinline__ float ldg_ef(const float* p) {
    float f;
    asm("{\n\t"
        ".reg .b64 ph;\n\t"
        "createpolicy.fractional.L2::evict_first.b64 ph, 1.0;\n\t"
        "ld.global.nc.L2::cache_hint.f32 %0, [%1], ph;\n\t"
        "}" : "=f"(f) : "l"(p));
    return f;
}
static __device__ __forceinline__ void stg_el(unsigned* p, unsigned v) {
    asm volatile("{\n\t"
        ".reg .b64 ph;\n\t"
        "createpolicy.fractional.L2::evict_last.b64 ph, 1.0;\n\t"
        "st.global.L2::cache_hint.b32 [%0], %1, ph;\n\t"
        "}" :: "l"(p), "r"(v) : "memory");
}
static __device__ __forceinline__ uint4 ldg_el128(const void* p) {
    uint4 v;
    asm("{\n\t"
        ".reg .b64 ph;\n\t"
        "createpolicy.fractional.L2::evict_last.b64 ph, 1.0;\n\t"
        "ld.global.nc.L2::cache_hint.v4.u32 {%0,%1,%2,%3}, [%4], ph;\n\t"
        "}"
        : "=r"(v.x), "=r"(v.y), "=r"(v.z), "=r"(v.w) : "l"(p));
    return v;
}

// ---------------- transpose NCHW f32 -> NHWC half (+ fused roi binning) ----
__global__ void __launch_bounds__(256) transpose_kernel(
    const float* __restrict__ feat,
    const float* __restrict__ rois)
{
    asm volatile("griddepcontrol.launch_dependents;" ::: "memory");

    __shared__ unsigned tile2[32][33];     // [w][cpair]
    __shared__ int hist[64];
    __shared__ int basec[64];

    const int tx = threadIdx.x;
    const int ty = threadIdx.y;
    const int w0 = blockIdx.x * 32;
    const int h  = blockIdx.y;
    const int z  = blockIdx.z;             // b*4 + ctile
    const int b  = z >> 2;
    const int c0 = (z & 3) * 64;

    // ---- fused roi binning in block (0,0,0); hidden behind other blocks ----
    if (blockIdx.x == 0 && blockIdx.y == 0 && blockIdx.z == 0) {
        const int tid = ty * 32 + tx;
        if (tid < 64) hist[tid] = 0;
        __syncthreads();
        int cell[2], rank[2];
#pragma unroll
        for (int i = 0; i < 2; ++i) {
            const int n = tid * 2 + i;
            const float cx = rois[n * 6 + 1] * 0.25f;
            const float cy = rois[n * 6 + 2] * 0.25f;
            int cxi = (int)((cx - 25.0f) * (8.0f / 150.0f));
            int cyi = (int)((cy - 25.0f) * (8.0f / 150.0f));
            cxi = min(7, max(0, cxi));
            cyi = min(7, max(0, cyi));
            cell[i] = cyi * 8 + cxi;
            rank[i] = atomicAdd(&hist[cell[i]], 1);
        }
        __syncthreads();
        if (tid == 0) {
            int a = 0;
#pragma unroll
            for (int i = 0; i < 64; ++i) { basec[i] = a; a += hist[i]; }
        }
        __syncthreads();
#pragma unroll
        for (int i = 0; i < 2; ++i)
            g_order[basec[cell[i]] + rank[i]] = tid * 2 + i;
        __syncthreads();
    }

    // ---- transpose tile ----
    const int w = w0 + tx;
#pragma unroll
    for (int k = 0; k < 4; ++k) {
        const int cp = ty + 8 * k;
        const int c  = c0 + 2 * cp;
        if (w < FW) {
            const float f0 = ldg_ef(feat + (((size_t)b * FC + c)     * FH + h) * FW + w);
            const float f1 = ldg_ef(feat + (((size_t)b * FC + c + 1) * FH + h) * FW + w);
            const __half2 v = __floats2half2_rn(f0, f1);
            tile2[tx][cp] = *(const unsigned*)&v;
        }
    }
    __syncthreads();
#pragma unroll
    for (int k = 0; k < 4; ++k) {
        const int wl = ty + 8 * k;
        const int w2 = w0 + wl;
        if (w2 < FW)
            stg_el(((unsigned*)g_h) + (((size_t)b * FH + h) * FW + w2) * (FC / 2)
                       + c0 / 2 + tx,
                   tile2[wl][tx]);
    }
}

// ------- gather: 2 CONCURRENT rois per 512-thread block (L1 dedup) --------
__global__ void __launch_bounds__(512, 2) gather_kernel(
    const float* __restrict__ rois,
    float* __restrict__ out)
{
    __shared__ int   s_base[2][196];
    __shared__ uint4 s_wh[2][196];
    __shared__ float s_acc[2][49][8][9];   // [half][bin][q8][8 ch + pad]

    // transpose's g_h AND g_order writes must be visible first
    asm volatile("griddepcontrol.wait;" ::: "memory");

    const int pair = blockIdx.x >> 2;          // 0..255
    const int ch0  = (blockIdx.x & 3) * 64;    // channel quarter
    const int tid  = threadIdx.x;              // 0..511
    const int half = tid >> 8;                 // which roi of the pair
    const int htid = tid & 255;

    const int n = g_order[pair * 2 + half];

    // ---- descriptors (each half independently) ----
    if (htid < 196) {
        const float* r = rois + n * 6;
        const int   b  = (int)r[0];
        const float cx = r[1] * 0.25f;
        const float cy = r[2] * 0.25f;
        const float rw = fmaxf(r[3] * 0.25f, 1.0f);
        const float rh = fmaxf(r[4] * 0.25f, 1.0f);
        float st, ct;
        __sincosf(r[5], &st, &ct);

        const float bin_w = rw * (1.0f / 7.0f);
        const float bin_h = rh * (1.0f / 7.0f);

        const int p  = htid >> 2;       // bin 0..48
        const int s  = htid & 3;        // sample 0..3
        const int ph = p / 7;
        const int pw = p - ph * 7;
        const float fh = ((float)(s >> 1) + 0.5f) * 0.5f;
        const float fw = ((float)(s & 1)  + 0.5f) * 0.5f;

        const float yy = -rh * 0.5f + ((float)ph + fh) * bin_h;
        const float xx = -rw * 0.5f + ((float)pw + fw) * bin_w;

        float x = xx * ct + yy * st + cx;
        float y = yy * ct - xx * st + cy;

        const bool valid = (y > -1.0f) && (y < (float)FH) &&
                           (x > -1.0f) && (x < (float)FW);

        y = fminf(fmaxf(y, 0.0f), (float)(FH - 1));
        x = fminf(fmaxf(x, 0.0f), (float)(FW - 1));

        const float y0f = fminf(floorf(y), (float)(FH - 2));
        const float x0f = fminf(floorf(x), (float)(FW - 2));

        const float ly = y - y0f;
        const float lx = x - x0f;
        const float hy = 1.0f - ly;
        const float hx = 1.0f - lx;
        const float m  = valid ? 0.25f : 0.0f;

        s_base[half][htid] = ((b * FH + (int)y0f) * FW + (int)x0f) * FC + ch0;

        const __half2 h00 = __float2half2_rn(hy * hx * m);
        const __half2 h01 = __float2half2_rn(hy * lx * m);
        const __half2 h10 = __float2half2_rn(ly * hx * m);
        const __half2 h11 = __float2half2_rn(ly * lx * m);
        uint4 wq;
        wq.x = *(const unsigned*)&h00;
        wq.y = *(const unsigned*)&h01;
        wq.z = *(const unsigned*)&h10;
        wq.w = *(const unsigned*)&h11;
        s_wh[half][htid] = wq;
    }
    __syncthreads();

    const int q8  = htid & 7;           // 8-channel group
    const int sub = (htid >> 3) & 3;    // bin sub-index within warp
    const int wid = htid >> 5;          // warp id 0..7 within half

    const int binA = wid * 4 + sub;            // 0..31 (always valid)
    const int binB = 32 + binA;                // 32..63
    const bool vB  = (binB < 49);
    const int dA   = binA * 4;
    const int dB   = vB ? binB * 4 : 0;        // invalid -> reuse bin0 (L1 hit)

    const int*   sb = s_base[half];
    const uint4* sw = s_wh[half];

    float accA[8] = {0.f,0.f,0.f,0.f,0.f,0.f,0.f,0.f};
    float accB[8] = {0.f,0.f,0.f,0.f,0.f,0.f,0.f,0.f};

#pragma unroll
    for (int s = 0; s < 4; ++s) {
        const int   baseA = sb[dA + s] + 8 * q8;
        const int   baseB = sb[dB + s] + 8 * q8;
        const uint4 wqA   = sw[dA + s];
        const uint4 wqB   = sw[dB + s];

        const uint4 ra0 = ldg_el128(g_h + baseA);
        const uint4 ra1 = ldg_el128(g_h + baseA + FC);
        const uint4 ra2 = ldg_el128(g_h + baseA + FW * FC);
        const uint4 ra3 = ldg_el128(g_h + baseA + FW * FC + FC);
        const uint4 rb0 = ldg_el128(g_h + baseB);
        const uint4 rb1 = ldg_el128(g_h + baseB + FC);
        const uint4 rb2 = ldg_el128(g_h + baseB + FW * FC);
        const uint4 rb3 = ldg_el128(g_h + baseB + FW * FC + FC);

        const unsigned* pa0 = &ra0.x;  const unsigned* pa1 = &ra1.x;
        const unsigned* pa2 = &ra2.x;  const unsigned* pa3 = &ra3.x;
        const unsigned* pb0 = &rb0.x;  const unsigned* pb1 = &rb1.x;
        const unsigned* pb2 = &rb2.x;  const unsigned* pb3 = &rb3.x;

        const __half2 wa0 = u2h(wqA.x), wa1 = u2h(wqA.y),
                      wa2 = u2h(wqA.z), wa3 = u2h(wqA.w);
        const __half2 wb0 = u2h(wqB.x), wb1 = u2h(wqB.y),
                      wb2 = u2h(wqB.z), wb3 = u2h(wqB.w);

#pragma unroll
        for (int j = 0; j < 4; ++j) {
            __half2 tA = __hmul2(wa0, u2h(pa0[j]));
            tA = __hfma2(wa1, u2h(pa1[j]), tA);
            tA = __hfma2(wa2, u2h(pa2[j]), tA);
            tA = __hfma2(wa3, u2h(pa3[j]), tA);
            const float2 fA = __half22float2(tA);
            accA[2*j]   += fA.x;
            accA[2*j+1] += fA.y;

            __half2 tB = __hmul2(wb0, u2h(pb0[j]));
            tB = __hfma2(wb1, u2h(pb1[j]), tB);
            tB = __hfma2(wb2, u2h(pb2[j]), tB);
            tB = __hfma2(wb3, u2h(pb3[j]), tB);
            const float2 fB = __half22float2(tB);
            accB[2*j]   += fB.x;
            accB[2*j+1] += fB.y;
        }
    }

#pragma unroll
    for (int j = 0; j < 8; ++j)
        s_acc[half][binA][q8][j] = accA[j];
    if (vB) {
#pragma unroll
        for (int j = 0; j < 8; ++j)
            s_acc[half][binB][q8][j] = accB[j];
    }
    __syncthreads();

    // coalesced writeout: out[n][ch0+c][bin]
    float* ob = out + n * PER_ROI + ch0 * 49;
    const float* sa = &s_acc[half][0][0][0];
#pragma unroll
    for (int i = htid; i < 64 * 49; i += 256) {
        const int c  = i / 49;
        const int bn = i - c * 49;
        ob[i] = sa[bn * 72 + (c >> 3) * 9 + (c & 7)];
    }
}

extern "C" void kernel_launch(void* const* d_in, const int* in_sizes, int n_in,
                              void* d_out, int out_size)
{
    const float* feat = (const float*)d_in[0];   // (2,256,200,200)
    const float* rois = (const float*)d_in[1];   // (512,6)
    float* out = (float*)d_out;                  // (512,256,7,7)

    transpose_kernel<<<dim3(7, FH, FB * 4), dim3(32, 8)>>>(feat, rois);

    cudaLaunchConfig_t cfg = {};
    cfg.gridDim  = dim3((NROI / 2) * 4);
    cfg.blockDim = dim3(512);
    cudaLaunchAttribute attr[1];
    attr[0].id = cudaLaunchAttributeProgrammaticStreamSerialization;
    attr[0].val.programmaticStreamSerializationAllowed = 1;
    cfg.attrs = attr;
    cfg.numAttrs = 1;
    cudaLaunchKernelEx(&cfg, gather_kernel, rois, out);
}

// round 17
// speedup vs baseline: 1.0949x; 1.0949x over previous
#include <cuda_runtime.h>
#include <cuda_fp16.h>

// RROIAlign via fp16-NHWC re-layout + L2 eviction hints + PDL (= R15 base,
// the measured optimum; all roi-locality variants regressed).
// Polish: transpose uses LDG.128 feature loads (1/4 the load instrs);
// output stores tagged evict_first so the once-written 26MB output doesn't
// displace the evict_last scratch in L2.

#define FB 2
#define FC 256
#define FH 200
#define FW 200
#define PER_ROI 12544      // 256*49

__device__ __half g_h[(size_t)FB * FH * FW * FC];   // 41 MB scratch

static __device__ __forceinline__ __half2 u2h(unsigned u) {
    __half2 h; *reinterpret_cast<unsigned*>(&h) = u; return h;
}

static __device__ __forceinline__ float4 ldg_ef128(const float* p) {
    float4 v;
    asm("{\n\t"
        ".reg .b64 ph;\n\t"
        "createpolicy.fractional.L2::evict_first.b64 ph, 1.0;\n\t"
        "ld.global.nc.L2::cache_hint.v4.f32 {%0,%1,%2,%3}, [%4], ph;\n\t"
        "}" : "=f"(v.x), "=f"(v.y), "=f"(v.z), "=f"(v.w) : "l"(p));
    return v;
}
static __device__ __forceinline__ float ldg_ef(const float* p) {
    float f;
    asm("{\n\t"
        ".reg .b64 ph;\n\t"
        "createpolicy.fractional.L2::evict_first.b64 ph, 1.0;\n\t"
        "ld.global.nc.L2::cache_hint.f32 %0, [%1], ph;\n\t"
        "}" : "=f"(f) : "l"(p));
    return f;
}
static __device__ __forceinline__ void stg_el(unsigned* p, unsigned v) {
    asm volatile("{\n\t"
        ".reg .b64 ph;\n\t"
        "createpolicy.fractional.L2::evict_last.b64 ph, 1.0;\n\t"
        "st.global.L2::cache_hint.b32 [%0], %1, ph;\n\t"
        "}" :: "l"(p), "r"(v) : "memory");
}
static __device__ __forceinline__ void stg_ef(float* p, float v) {
    asm volatile("{\n\t"
        ".reg .b64 ph;\n\t"
        "createpolicy.fractional.L2::evict_first.b64 ph, 1.0;\n\t"
        "st.global.L2::cache_hint.f32 [%0], %1, ph;\n\t"
        "}" :: "l"(p), "f"(v) : "memory");
}
static __device__ __forceinline__ uint4 ldg_el128(const void* p) {
    uint4 v;
    asm("{\n\t"
        ".reg .b64 ph;\n\t"
        "createpolicy.fractional.L2::evict_last.b64 ph, 1.0;\n\t"
        "ld.global.nc.L2::cache_hint.v4.u32 {%0,%1,%2,%3}, [%4], ph;\n\t"
        "}"
        : "=r"(v.x), "=r"(v.y), "=r"(v.z), "=r"(v.w) : "l"(p));
    return v;
}

// ---------------- transpose NCHW f32 -> NHWC half ----------------
// block (32,8); tile 64 ch x 32 w. Loads: 2x LDG.128/thread (fast path),
// scalar fallback for the W-boundary tile. Pack to half2 at store phase.
__global__ void __launch_bounds__(256) transpose_kernel(const float* __restrict__ feat)
{
    asm volatile("griddepcontrol.launch_dependents;" ::: "memory");

    __shared__ float tileF[64][33];
    const int tx = threadIdx.x;
    const int ty = threadIdx.y;
    const int t  = ty * 32 + tx;           // 0..255
    const int w0 = blockIdx.x * 32;
    const int h  = blockIdx.y;
    const int z  = blockIdx.z;             // b*4 + ctile
    const int b  = z >> 2;
    const int c0 = (z & 3) * 64;

    if (w0 + 32 <= FW) {
        // fast path: float4 loads; thread t covers (c_local = t/8 + 32k, 4 w)
#pragma unroll
        for (int k = 0; k < 2; ++k) {
            const int cl = (t >> 3) + 32 * k;
            const int w4 = (t & 7) * 4;
            const float4 v = ldg_ef128(
                feat + (((size_t)b * FC + c0 + cl) * FH + h) * FW + w0 + w4);
            tileF[cl][w4 + 0] = v.x;
            tileF[cl][w4 + 1] = v.y;
            tileF[cl][w4 + 2] = v.z;
            tileF[cl][w4 + 3] = v.w;
        }
    } else {
        // boundary tile (w0=192): scalar loads
#pragma unroll
        for (int k = 0; k < 8; ++k) {
            const int cl = ty + 8 * k;
            const int w  = w0 + tx;
            if (w < FW)
                tileF[cl][tx] = ldg_ef(
                    feat + (((size_t)b * FC + c0 + cl) * FH + h) * FW + w);
        }
    }
    __syncthreads();

    // store: warp = fixed w, lanes = half2 along channels (128B/warp)
#pragma unroll
    for (int k = 0; k < 4; ++k) {
        const int wl = ty + 8 * k;
        const int w2 = w0 + wl;
        if (w2 < FW) {
            const __half2 v = __floats2half2_rn(tileF[2 * tx][wl], tileF[2 * tx + 1][wl]);
            stg_el(((unsigned*)g_h) + (((size_t)b * FH + h) * FW + w2) * (FC / 2)
                       + c0 / 2 + tx,
                   *(const unsigned*)&v);
        }
    }
}

// ---------------- gather ----------------
__global__ void __launch_bounds__(256, 4) gather_kernel(
    const float* __restrict__ rois,
    float* __restrict__ out)
{
    __shared__ int   s_base[196];
    __shared__ uint4 s_wh[196];            // 4x half2-broadcast weights
    __shared__ float s_acc[49][8][9];      // [bin][q8][8 ch + pad]

    const int n   = blockIdx.x >> 2;           // roi
    const int ch0 = (blockIdx.x & 3) * 64;     // channel quarter
    const int tid = threadIdx.x;

    // ---- prologue (independent of transpose output; overlaps via PDL) ----
    if (tid < 196) {
        const float* r = rois + n * 6;
        const int   b  = (int)r[0];
        const float cx = r[1] * 0.25f;
        const float cy = r[2] * 0.25f;
        const float rw = fmaxf(r[3] * 0.25f, 1.0f);
        const float rh = fmaxf(r[4] * 0.25f, 1.0f);
        float st, ct;
        __sincosf(r[5], &st, &ct);

        const float bin_w = rw * (1.0f / 7.0f);
        const float bin_h = rh * (1.0f / 7.0f);

        const int p  = tid >> 2;        // bin 0..48
        const int s  = tid & 3;         // sample 0..3
        const int ph = p / 7;
        const int pw = p - ph * 7;
        const float fh = ((float)(s >> 1) + 0.5f) * 0.5f;
        const float fw = ((float)(s & 1)  + 0.5f) * 0.5f;

        const float yy = -rh * 0.5f + ((float)ph + fh) * bin_h;
        const float xx = -rw * 0.5f + ((float)pw + fw) * bin_w;

        float x = xx * ct + yy * st + cx;
        float y = yy * ct - xx * st + cy;

        const bool valid = (y > -1.0f) && (y < (float)FH) &&
                           (x > -1.0f) && (x < (float)FW);

        y = fminf(fmaxf(y, 0.0f), (float)(FH - 1));
        x = fminf(fmaxf(x, 0.0f), (float)(FW - 1));

        const float y0f = fminf(floorf(y), (float)(FH - 2));
        const float x0f = fminf(floorf(x), (float)(FW - 2));

        const float ly = y - y0f;
        const float lx = x - x0f;
        const float hy = 1.0f - ly;
        const float hx = 1.0f - lx;
        const float m  = valid ? 0.25f : 0.0f;

        s_base[tid] = ((b * FH + (int)y0f) * FW + (int)x0f) * FC + ch0;

        const __half2 h00 = __float2half2_rn(hy * hx * m);
        const __half2 h01 = __float2half2_rn(hy * lx * m);
        const __half2 h10 = __float2half2_rn(ly * hx * m);
        const __half2 h11 = __float2half2_rn(ly * lx * m);
        uint4 wq;
        wq.x = *(const unsigned*)&h00;
        wq.y = *(const unsigned*)&h01;
        wq.z = *(const unsigned*)&h10;
        wq.w = *(const unsigned*)&h11;
        s_wh[tid] = wq;
    }
    __syncthreads();

    // wait until the transpose's writes to g_h are visible
    asm volatile("griddepcontrol.wait;" ::: "memory");

    const int q8  = tid & 7;            // 8-channel group
    const int sub = (tid >> 3) & 3;     // bin sub-index within warp
    const int wid = tid >> 5;           // warp id 0..7

    const int binA = wid * 4 + sub;            // 0..31 (always valid)
    const int binB = 32 + binA;                // 32..63
    const bool vB  = (binB < 49);
    const int dA   = binA * 4;
    const int dB   = vB ? binB * 4 : 0;        // invalid -> reuse bin0 (L1 hit)

    float accA[8] = {0.f,0.f,0.f,0.f,0.f,0.f,0.f,0.f};
    float accB[8] = {0.f,0.f,0.f,0.f,0.f,0.f,0.f,0.f};

#pragma unroll
    for (int s = 0; s < 4; ++s) {
        const int   baseA = s_base[dA + s] + 8 * q8;
        const int   baseB = s_base[dB + s] + 8 * q8;
        const uint4 wqA   = s_wh[dA + s];
        const uint4 wqB   = s_wh[dB + s];

        const uint4 ra0 = ldg_el128(g_h + baseA);
        const uint4 ra1 = ldg_el128(g_h + baseA + FC);
        const uint4 ra2 = ldg_el128(g_h + baseA + FW * FC);
        const uint4 ra3 = ldg_el128(g_h + baseA + FW * FC + FC);
        const uint4 rb0 = ldg_el128(g_h + baseB);
        const uint4 rb1 = ldg_el128(g_h + baseB + FC);
        const uint4 rb2 = ldg_el128(g_h + baseB + FW * FC);
        const uint4 rb3 = ldg_el128(g_h + baseB + FW * FC + FC);

        const unsigned* pa0 = &ra0.x;  const unsigned* pa1 = &ra1.x;
        const unsigned* pa2 = &ra2.x;  const unsigned* pa3 = &ra3.x;
        const unsigned* pb0 = &rb0.x;  const unsigned* pb1 = &rb1.x;
        const unsigned* pb2 = &rb2.x;  const unsigned* pb3 = &rb3.x;

        const __half2 wa0 = u2h(wqA.x), wa1 = u2h(wqA.y),
                      wa2 = u2h(wqA.z), wa3 = u2h(wqA.w);
        const __half2 wb0 = u2h(wqB.x), wb1 = u2h(wqB.y),
                      wb2 = u2h(wqB.z), wb3 = u2h(wqB.w);

#pragma unroll
        for (int j = 0; j < 4; ++j) {
            __half2 tA = __hmul2(wa0, u2h(pa0[j]));
            tA = __hfma2(wa1, u2h(pa1[j]), tA);
            tA = __hfma2(wa2, u2h(pa2[j]), tA);
            tA = __hfma2(wa3, u2h(pa3[j]), tA);
            const float2 fA = __half22float2(tA);
            accA[2*j]   += fA.x;
            accA[2*j+1] += fA.y;

            __half2 tB = __hmul2(wb0, u2h(pb0[j]));
            tB = __hfma2(wb1, u2h(pb1[j]), tB);
            tB = __hfma2(wb2, u2h(pb2[j]), tB);
            tB = __hfma2(wb3, u2h(pb3[j]), tB);
            const float2 fB = __half22float2(tB);
            accB[2*j]   += fB.x;
            accB[2*j+1] += fB.y;
        }
    }

#pragma unroll
    for (int j = 0; j < 8; ++j)
        s_acc[binA][q8][j] = accA[j];
    if (vB) {
#pragma unroll
        for (int j = 0; j < 8; ++j)
            s_acc[binB][q8][j] = accB[j];
    }
    __syncthreads();

    // coalesced writeout (evict_first: output never re-read)
    float* ob = out + n * PER_ROI + ch0 * 49;
    const float* sa = &s_acc[0][0][0];
#pragma unroll
    for (int i = tid; i < 64 * 49; i += 256) {
        const int c  = i / 49;
        const int bn = i - c * 49;
        stg_ef(ob + i, sa[bn * 72 + (c >> 3) * 9 + (c & 7)]);
    }
}

extern "C" void kernel_launch(void* const* d_in, const int* in_sizes, int n_in,
                              void* d_out, int out_size)
{
    const float* feat = (const float*)d_in[0];   // (2,256,200,200)
    const float* rois = (const float*)d_in[1];   // (512,6)
    float* out = (float*)d_out;                  // (512,256,7,7)

    const int n_rois = in_sizes[1] / 6;          // 512

    transpose_kernel<<<dim3(7, FH, FB * 4), dim3(32, 8)>>>(feat);

    cudaLaunchConfig_t cfg = {};
    cfg.gridDim  = dim3(n_rois * 4);
    cfg.blockDim = dim3(256);
    cudaLaunchAttribute attr[1];
    attr[0].id = cudaLaunchAttributeProgrammaticStreamSerialization;
    attr[0].val.programmaticStreamSerializationAllowed = 1;
    cfg.attrs = attr;
    cfg.numAttrs = 1;
    cudaLaunchKernelEx(&cfg, gather_kernel, rois, out);
}